// round 7
// baseline (speedup 1.0000x reference)
#include <cuda_runtime.h>
#include <cuda_fp16.h>
#include <stdint.h>
#include <math.h>

#define B_ 8
#define S_ 4096
#define D_ 1024
#define R_ 64

// ---------------- scratch (no allocations allowed) ----------------
__device__ __align__(16) __half g_xqh[B_ * S_ * R_];   // 4 MB: fp16(x @ Q / 32)
__device__ __align__(16) __half g_xTh[B_ * D_ * S_];   // 64 MB: fp16(x)^T [B][D][S]
__device__ float g_inv[B_ * S_];                        // 1 / sum_n exp(logit)

// ---------------- helpers ----------------
__device__ __forceinline__ uint32_t smem_u32(const void *p) {
    uint32_t a;
    asm("{ .reg .u64 t; cvta.to.shared.u64 t, %1; cvt.u32.u64 %0, t; }" : "=r"(a) : "l"(p));
    return a;
}
__device__ __forceinline__ void ffma2(float2 &c, const float2 a, const float2 b) {
    asm("fma.rn.f32x2 %0, %1, %2, %0;"
        : "+l"(*reinterpret_cast<unsigned long long *>(&c))
        : "l"(*reinterpret_cast<const unsigned long long *>(&a)),
          "l"(*reinterpret_cast<const unsigned long long *>(&b)));
}
__device__ __forceinline__ void cpa16(uint32_t dst, const void *src) {
    asm volatile("cp.async.cg.shared.global [%0], [%1], 16;" :: "r"(dst), "l"(src));
}
#define CP_COMMIT() asm volatile("cp.async.commit_group;" ::: "memory")
#define CP_WAIT0()  asm volatile("cp.async.wait_group 0;" ::: "memory")

// fp16 tensor-core mma: D(16x8,f32) += A(16x16,f16) * B(16x8,f16)
__device__ __forceinline__ void mma_f16(float *d, const uint32_t *a, const uint32_t *b) {
    asm volatile(
        "mma.sync.aligned.m16n8k16.row.col.f32.f16.f16.f32 "
        "{%0,%1,%2,%3}, {%4,%5,%6,%7}, {%8,%9}, {%0,%1,%2,%3};"
        : "+f"(d[0]), "+f"(d[1]), "+f"(d[2]), "+f"(d[3])
        : "r"(a[0]), "r"(a[1]), "r"(a[2]), "r"(a[3]), "r"(b[0]), "r"(b[1]));
}

// ---------------- k_main smem half offsets (row pad 72 halves) ----------------
#define HO_XQQ 0          // [128][72] h
#define HO_XQK 9216       // [64][72] h (single buffer)
#define HO_PS  13824      // [128][72] h
#define HO_XV0 23040      // [256][72] h (x^T: rows=d, cols=keys)
#define HO_XV1 41472
#define SMM_MAIN (59904 * 2)    // 119,808 B

// ---------------- k_stats smem ----------------
#define SO_XQQ 0
#define SO_XQK0 9216
#define SO_XQK1 13824
#define SO_REDB 36864     // byte offset of 512-float reduction area
#define SMM_STATS (36864 + 2048)

// tile loader: rows x 64 halves, row stride stride_h (halves), pad-72 dst
__device__ __forceinline__ void ld_tileh(uint32_t sb, int fo_h, const __half *src,
                                         size_t stride_h, int rows, int tid, int nthr) {
    int total = rows * 8;
    for (int idx = tid; idx < total; idx += nthr) {
        int r = idx >> 3, c8 = idx & 7;
        cpa16(sb + (uint32_t)(fo_h + r * 72 + c8 * 8) * 2u,
              src + (size_t)r * stride_h + c8 * 8);
    }
}

// =====================================================================
// Kernel 1: g_xqh = fp16( (x @ Q) / 32 )  (FFMA2, proven)
// =====================================================================
__global__ void __launch_bounds__(256) k_proj(const float *__restrict__ x,
                                              const float *__restrict__ Q) {
    extern __shared__ float sm[];
    float *Xs = sm;
    float *Qs = sm + 128 * 68;
    const int t = threadIdx.x;
    const int row0 = blockIdx.x * 128;
    const int ty = t >> 3, tx = t & 7;

    float2 acc[4][4];
#pragma unroll
    for (int i = 0; i < 4; i++)
#pragma unroll
        for (int p = 0; p < 4; p++) acc[i][p] = make_float2(0.f, 0.f);

    for (int dc = 0; dc < 16; dc++) {
        const int d0 = dc * 64;
#pragma unroll
        for (int i = 0; i < 8; i++) {
            int f = t + i * 256;
            int r = f >> 4, c4 = f & 15;
            float4 v = *reinterpret_cast<const float4 *>(x + (size_t)(row0 + r) * D_ + d0 + c4 * 4);
            *reinterpret_cast<float4 *>(Xs + r * 68 + c4 * 4) = v;
        }
#pragma unroll
        for (int i = 0; i < 4; i++) {
            int f = t + i * 256;
            int r = f >> 4, c4 = f & 15;
            float4 v = *reinterpret_cast<const float4 *>(Q + (size_t)(d0 + r) * R_ + c4 * 4);
            *reinterpret_cast<float4 *>(Qs + r * 68 + c4 * 4) = v;
        }
        __syncthreads();
#pragma unroll 4
        for (int dd = 0; dd < 64; dd++) {
            float2 aa[4];
#pragma unroll
            for (int i = 0; i < 4; i++) {
                float a = Xs[(ty * 4 + i) * 68 + dd];
                aa[i] = make_float2(a, a);
            }
            float4 q0 = *reinterpret_cast<const float4 *>(Qs + dd * 68 + tx * 8);
            float4 q1 = *reinterpret_cast<const float4 *>(Qs + dd * 68 + tx * 8 + 4);
            float2 bb[4] = {make_float2(q0.x, q0.y), make_float2(q0.z, q0.w),
                            make_float2(q1.x, q1.y), make_float2(q1.z, q1.w)};
#pragma unroll
            for (int i = 0; i < 4; i++)
#pragma unroll
                for (int p = 0; p < 4; p++) ffma2(acc[i][p], aa[i], bb[p]);
        }
        __syncthreads();
    }
    const float scale = 0.03125f;
#pragma unroll
    for (int i = 0; i < 4; i++) {
        __half *dst = g_xqh + (size_t)(row0 + ty * 4 + i) * R_ + tx * 8;
        __half2 h0 = __floats2half2_rn(acc[i][0].x * scale, acc[i][0].y * scale);
        __half2 h1 = __floats2half2_rn(acc[i][1].x * scale, acc[i][1].y * scale);
        __half2 h2 = __floats2half2_rn(acc[i][2].x * scale, acc[i][2].y * scale);
        __half2 h3 = __floats2half2_rn(acc[i][3].x * scale, acc[i][3].y * scale);
        uint4 pk;
        pk.x = *reinterpret_cast<uint32_t *>(&h0);
        pk.y = *reinterpret_cast<uint32_t *>(&h1);
        pk.z = *reinterpret_cast<uint32_t *>(&h2);
        pk.w = *reinterpret_cast<uint32_t *>(&h3);
        *reinterpret_cast<uint4 *>(dst) = pk;
    }
}

// =====================================================================
// Kernel 2: g_xTh[b][d][s] = fp16( x[b][s][d] )
// =====================================================================
__global__ void __launch_bounds__(256) k_tr(const float *__restrict__ x) {
    __shared__ float tile[32][33];
    const int b = blockIdx.z;
    const int s0 = blockIdx.x * 32;
    const int d0 = blockIdx.y * 32;
    const int tx = threadIdx.x & 31, ty = threadIdx.x >> 5;
    const float *src = x + ((size_t)b * S_ + s0) * D_ + d0;
#pragma unroll
    for (int i = 0; i < 4; i++) {
        int r = ty + i * 8;
        tile[r][tx] = src[(size_t)r * D_ + tx];
    }
    __syncthreads();
    __half *dst = g_xTh + ((size_t)b * D_ + d0) * S_ + s0;
#pragma unroll
    for (int i = 0; i < 4; i++) {
        int r = ty + i * 8;
        dst[(size_t)r * S_ + tx] = __float2half_rn(tile[tx][r]);
    }
}

// =====================================================================
// Kernel 3: stats — g_inv[row] = 1 / sum_n exp(logit[row][n])
// 256 threads, warp grid 2m x 4n (proven). Same mma as k_main stage1.
// =====================================================================
__global__ void __launch_bounds__(256) k_stats() {
    extern __shared__ char smc[];
    __half *smh = reinterpret_cast<__half *>(smc);
    const uint32_t sb = smem_u32(smc);
    const int tid = threadIdx.x, w = tid >> 5, lane = tid & 31;
    const int g = lane >> 2, tg = lane & 3;
    const int wm = w >> 2, wn = w & 3;
    const int m0 = wm * 64, n0s = wn * 16;
    const int q0 = blockIdx.x * 128;
    const int bb = q0 / S_;
    const __half *xqq = g_xqh + (size_t)q0 * R_;
    const __half *xqk = g_xqh + (size_t)bb * S_ * R_;

    ld_tileh(sb, SO_XQQ, xqq, R_, 128, tid, 256);
    ld_tileh(sb, SO_XQK0, xqk, R_, 64, tid, 256);
    CP_COMMIT();
    CP_WAIT0();
    __syncthreads();

    float rsum[4][2];
#pragma unroll
    for (int mi = 0; mi < 4; mi++) { rsum[mi][0] = 0.f; rsum[mi][1] = 0.f; }

    for (int kb = 0; kb < 64; kb++) {
        if (kb + 1 < 64) {
            ld_tileh(sb, ((kb + 1) & 1) ? SO_XQK1 : SO_XQK0,
                     xqk + (size_t)(kb + 1) * 64 * R_, R_, 64, tid, 256);
            CP_COMMIT();
        }
        const __half *XQ = smh + SO_XQQ;
        const __half *XK = smh + ((kb & 1) ? SO_XQK1 : SO_XQK0);
        float sacc[4][2][4];
#pragma unroll
        for (int mi = 0; mi < 4; mi++)
#pragma unroll
            for (int ni = 0; ni < 2; ni++)
#pragma unroll
                for (int c = 0; c < 4; c++) sacc[mi][ni][c] = 0.f;
#pragma unroll
        for (int kk = 0; kk < 4; kk++) {
            uint32_t a[4][4], bf[2][2];
            const int c = kk * 16 + 2 * tg;
#pragma unroll
            for (int mi = 0; mi < 4; mi++) {
                int r = m0 + mi * 16 + g;
                a[mi][0] = *reinterpret_cast<const uint32_t *>(XQ + r * 72 + c);
                a[mi][1] = *reinterpret_cast<const uint32_t *>(XQ + (r + 8) * 72 + c);
                a[mi][2] = *reinterpret_cast<const uint32_t *>(XQ + r * 72 + c + 8);
                a[mi][3] = *reinterpret_cast<const uint32_t *>(XQ + (r + 8) * 72 + c + 8);
            }
#pragma unroll
            for (int ni = 0; ni < 2; ni++) {
                int n = n0s + ni * 8 + g;
                bf[ni][0] = *reinterpret_cast<const uint32_t *>(XK + n * 72 + c);
                bf[ni][1] = *reinterpret_cast<const uint32_t *>(XK + n * 72 + c + 8);
            }
#pragma unroll
            for (int mi = 0; mi < 4; mi++)
#pragma unroll
                for (int ni = 0; ni < 2; ni++) mma_f16(sacc[mi][ni], a[mi], bf[ni]);
        }
#pragma unroll
        for (int mi = 0; mi < 4; mi++)
#pragma unroll
            for (int ni = 0; ni < 2; ni++) {
                rsum[mi][0] += __expf(sacc[mi][ni][0]) + __expf(sacc[mi][ni][1]);
                rsum[mi][1] += __expf(sacc[mi][ni][2]) + __expf(sacc[mi][ni][3]);
            }
        if (kb + 1 < 64) CP_WAIT0();
        __syncthreads();
    }
#pragma unroll
    for (int off = 1; off <= 2; off <<= 1)
#pragma unroll
        for (int mi = 0; mi < 4; mi++) {
            rsum[mi][0] += __shfl_xor_sync(0xffffffffu, rsum[mi][0], off);
            rsum[mi][1] += __shfl_xor_sync(0xffffffffu, rsum[mi][1], off);
        }
    float *red = reinterpret_cast<float *>(smc + SO_REDB);  // 4 x 128
    if (tg == 0) {
#pragma unroll
        for (int mi = 0; mi < 4; mi++) {
            red[wn * 128 + m0 + mi * 16 + g] = rsum[mi][0];
            red[wn * 128 + m0 + mi * 16 + 8 + g] = rsum[mi][1];
        }
    }
    __syncthreads();
    if (tid < 128) {
        float s = red[tid] + red[128 + tid] + red[256 + tid] + red[384 + tid];
        g_inv[q0 + tid] = 1.0f / s;
    }
}

// =====================================================================
// Kernel 4: flash main (fp16 mma, 512 threads / 16 warps).
// warp grid 4m x 4n: stage1 tile 32m x 16n, stage2 tile 32m x 64n.
// =====================================================================
__global__ void __launch_bounds__(512, 1) k_main(float *__restrict__ out) {
    extern __shared__ char smc[];
    __half *smh = reinterpret_cast<__half *>(smc);
    const uint32_t sb = smem_u32(smc);
    const int tid = threadIdx.x, w = tid >> 5, lane = tid & 31;
    const int g = lane >> 2, tg = lane & 3;
    const int wm = w >> 2, wn = w & 3;
    const int m0 = wm * 32, n0s = wn * 16, n0 = wn * 64;
    const int b = blockIdx.z, q0 = blockIdx.x * 128, d0 = blockIdx.y * 256;

    const __half *xqq = g_xqh + ((size_t)b * S_ + q0) * R_;
    const __half *xqk = g_xqh + (size_t)b * S_ * R_;
    const __half *xvt = g_xTh + ((size_t)b * D_ + d0) * S_;  // rows=d (256), cols=s

    ld_tileh(sb, HO_XQQ, xqq, R_, 128, tid, 512);
    ld_tileh(sb, HO_XQK, xqk, R_, 64, tid, 512);
    ld_tileh(sb, HO_XV0, xvt, S_, 256, tid, 512);
    CP_COMMIT();
    CP_WAIT0();
    __syncthreads();

    float ri[2][2];
#pragma unroll
    for (int mi = 0; mi < 2; mi++) {
        ri[mi][0] = g_inv[(size_t)b * S_ + q0 + m0 + mi * 16 + g];
        ri[mi][1] = g_inv[(size_t)b * S_ + q0 + m0 + mi * 16 + 8 + g];
    }

    float yacc[2][8][4];
#pragma unroll
    for (int mi = 0; mi < 2; mi++)
#pragma unroll
        for (int nj = 0; nj < 8; nj++)
#pragma unroll
            for (int c = 0; c < 4; c++) yacc[mi][nj][c] = 0.f;

    for (int kb = 0; kb < 64; kb++) {
        // ---- stage1: logits (32m x 16n) ----
        float sacc[2][2][4];
#pragma unroll
        for (int mi = 0; mi < 2; mi++)
#pragma unroll
            for (int ni = 0; ni < 2; ni++)
#pragma unroll
                for (int c = 0; c < 4; c++) sacc[mi][ni][c] = 0.f;
        {
            const __half *XQ = smh + HO_XQQ;
            const __half *XK = smh + HO_XQK;
#pragma unroll
            for (int kk = 0; kk < 4; kk++) {
                uint32_t a[2][4], bf[2][2];
                const int c = kk * 16 + 2 * tg;
#pragma unroll
                for (int mi = 0; mi < 2; mi++) {
                    int r = m0 + mi * 16 + g;
                    a[mi][0] = *reinterpret_cast<const uint32_t *>(XQ + r * 72 + c);
                    a[mi][1] = *reinterpret_cast<const uint32_t *>(XQ + (r + 8) * 72 + c);
                    a[mi][2] = *reinterpret_cast<const uint32_t *>(XQ + r * 72 + c + 8);
                    a[mi][3] = *reinterpret_cast<const uint32_t *>(XQ + (r + 8) * 72 + c + 8);
                }
#pragma unroll
                for (int ni = 0; ni < 2; ni++) {
                    int n = n0s + ni * 8 + g;
                    bf[ni][0] = *reinterpret_cast<const uint32_t *>(XK + n * 72 + c);
                    bf[ni][1] = *reinterpret_cast<const uint32_t *>(XK + n * 72 + c + 8);
                }
#pragma unroll
                for (int mi = 0; mi < 2; mi++)
#pragma unroll
                    for (int ni = 0; ni < 2; ni++) mma_f16(sacc[mi][ni], a[mi], bf[ni]);
            }
        }

        // ---- P = fp16(exp(S) * inv) -> smem ----
#pragma unroll
        for (int mi = 0; mi < 2; mi++)
#pragma unroll
            for (int ni = 0; ni < 2; ni++) {
                int r0 = m0 + mi * 16 + g;
                int cc = n0s + ni * 8 + 2 * tg;
                __half2 p0 = __floats2half2_rn(__expf(sacc[mi][ni][0]) * ri[mi][0],
                                               __expf(sacc[mi][ni][1]) * ri[mi][0]);
                __half2 p1 = __floats2half2_rn(__expf(sacc[mi][ni][2]) * ri[mi][1],
                                               __expf(sacc[mi][ni][3]) * ri[mi][1]);
                *reinterpret_cast<__half2 *>(smh + HO_PS + r0 * 72 + cc) = p0;
                *reinterpret_cast<__half2 *>(smh + HO_PS + (r0 + 8) * 72 + cc) = p1;
            }
        __syncthreads();  // stage1 everywhere done; P visible; prev stage2 done

        // ---- prefetch kb+1 ----
        if (kb + 1 < 64) {
            ld_tileh(sb, HO_XQK, xqk + (size_t)(kb + 1) * 64 * R_, R_, 64, tid, 512);
            ld_tileh(sb, ((kb + 1) & 1) ? HO_XV1 : HO_XV0,
                     xvt + (size_t)(kb + 1) * 64, S_, 256, tid, 512);
            CP_COMMIT();
        }

        // ---- stage2: Y += P @ XvT^T (32m x 64n, K=64, 4 k16-steps) ----
        const __half *PS = smh + HO_PS;
        const __half *XV = smh + ((kb & 1) ? HO_XV1 : HO_XV0);
#pragma unroll
        for (int kk = 0; kk < 4; kk++) {
            uint32_t a[2][4], bf[8][2];
            const int c = kk * 16 + 2 * tg;
#pragma unroll
            for (int mi = 0; mi < 2; mi++) {
                int r = m0 + mi * 16 + g;
                a[mi][0] = *reinterpret_cast<const uint32_t *>(PS + r * 72 + c);
                a[mi][1] = *reinterpret_cast<const uint32_t *>(PS + (r + 8) * 72 + c);
                a[mi][2] = *reinterpret_cast<const uint32_t *>(PS + r * 72 + c + 8);
                a[mi][3] = *reinterpret_cast<const uint32_t *>(PS + (r + 8) * 72 + c + 8);
            }
#pragma unroll
            for (int nj = 0; nj < 8; nj++) {
                int n = n0 + nj * 8 + g;
                bf[nj][0] = *reinterpret_cast<const uint32_t *>(XV + n * 72 + c);
                bf[nj][1] = *reinterpret_cast<const uint32_t *>(XV + n * 72 + c + 8);
            }
#pragma unroll
            for (int mi = 0; mi < 2; mi++)
#pragma unroll
                for (int nj = 0; nj < 8; nj++) mma_f16(yacc[mi][nj], a[mi], bf[nj]);
        }
        if (kb + 1 < 64) CP_WAIT0();
        __syncthreads();
    }

    // ---- epilogue ----
#pragma unroll
    for (int mi = 0; mi < 2; mi++) {
        size_t rbase = ((size_t)b * S_ + q0 + m0 + mi * 16 + g) * D_ + d0 + n0 + 2 * tg;
#pragma unroll
        for (int nj = 0; nj < 8; nj++) {
            *reinterpret_cast<float2 *>(out + rbase + nj * 8) =
                make_float2(yacc[mi][nj][0], yacc[mi][nj][1]);
            *reinterpret_cast<float2 *>(out + rbase + nj * 8 + (size_t)8 * D_) =
                make_float2(yacc[mi][nj][2], yacc[mi][nj][3]);
        }
    }
}

// =====================================================================
extern "C" void kernel_launch(void *const *d_in, const int *in_sizes, int n_in,
                              void *d_out, int out_size) {
    const float *x = (const float *)d_in[0];
    const float *Q = (const float *)d_in[1];
    float *out = (float *)d_out;

    const int SM1 = (128 * 68 + 64 * 68) * 4;
    cudaFuncSetAttribute(k_proj, cudaFuncAttributeMaxDynamicSharedMemorySize, SM1);
    cudaFuncSetAttribute(k_stats, cudaFuncAttributeMaxDynamicSharedMemorySize, SMM_STATS);
    cudaFuncSetAttribute(k_main, cudaFuncAttributeMaxDynamicSharedMemorySize, SMM_MAIN);

    k_proj<<<(B_ * S_) / 128, 256, SM1>>>(x, Q);
    k_tr<<<dim3(S_ / 32, D_ / 32, B_), 256>>>(x);
    k_stats<<<(B_ * S_) / 128, 256, SMM_STATS>>>();
    k_main<<<dim3(S_ / 128, D_ / 256, B_), 512, SMM_MAIN>>>(out);
}

// round 8
// speedup vs baseline: 1.2606x; 1.2606x over previous
#include <cuda_runtime.h>
#include <cuda_fp16.h>
#include <stdint.h>
#include <math.h>

#define B_ 8
#define S_ 4096
#define D_ 1024
#define R_ 64

// ---------------- scratch (no allocations allowed) ----------------
__device__ __align__(16) __half g_xqh[B_ * S_ * R_];    // 4 MB fp16(x@Q/32)
__device__ __align__(16) __half g_xTh[B_ * D_ * S_];    // 64 MB fp16(x)^T [B][D][S]
__device__ __align__(16) __half g_ph[(size_t)B_ * S_ * S_];  // 268 MB P~ = fp16(exp(S))
__device__ float g_part[B_ * 32 * S_];                   // per-n-tile row sums
__device__ float g_inv[B_ * S_];                         // 1 / sum

// ---------------- helpers ----------------
__device__ __forceinline__ uint32_t smem_u32(const void *p) {
    uint32_t a;
    asm("{ .reg .u64 t; cvta.to.shared.u64 t, %1; cvt.u32.u64 %0, t; }" : "=r"(a) : "l"(p));
    return a;
}
__device__ __forceinline__ void ffma2(float2 &c, const float2 a, const float2 b) {
    asm("fma.rn.f32x2 %0, %1, %2, %0;"
        : "+l"(*reinterpret_cast<unsigned long long *>(&c))
        : "l"(*reinterpret_cast<const unsigned long long *>(&a)),
          "l"(*reinterpret_cast<const unsigned long long *>(&b)));
}
__device__ __forceinline__ void cpa16(uint32_t dst, const void *src) {
    asm volatile("cp.async.cg.shared.global [%0], [%1], 16;" :: "r"(dst), "l"(src));
}
#define CP_COMMIT() asm volatile("cp.async.commit_group;" ::: "memory")
#define CP_WAIT0()  asm volatile("cp.async.wait_group 0;" ::: "memory")

__device__ __forceinline__ void mma_f16(float *d, const uint32_t *a, const uint32_t *b) {
    asm volatile(
        "mma.sync.aligned.m16n8k16.row.col.f32.f16.f16.f32 "
        "{%0,%1,%2,%3}, {%4,%5,%6,%7}, {%8,%9}, {%0,%1,%2,%3};"
        : "+f"(d[0]), "+f"(d[1]), "+f"(d[2]), "+f"(d[3])
        : "r"(a[0]), "r"(a[1]), "r"(a[2]), "r"(a[3]), "r"(b[0]), "r"(b[1]));
}

// tile loader: rows x 64 halves, row stride stride_h (halves), pad-72 dst
__device__ __forceinline__ void ld_tileh(uint32_t sb, int fo_h, const __half *src,
                                         size_t stride_h, int rows, int tid, int nthr) {
    int total = rows * 8;
    for (int idx = tid; idx < total; idx += nthr) {
        int r = idx >> 3, c8 = idx & 7;
        cpa16(sb + (uint32_t)(fo_h + r * 72 + c8 * 8) * 2u,
              src + (size_t)r * stride_h + c8 * 8);
    }
}

// ---------------- k_qkexp smem (half offsets) ----------------
#define QO_A 0            // [128][72]
#define QO_B 9216         // [128][72]
#define QO_REDB 36864     // byte offset: 4x128 floats
#define SMM_QK (36864 + 2048)

// ---------------- k_pv smem (half offsets) ----------------
#define PO_P0 0           // [128][72]
#define PO_P1 9216
#define PO_XV0 18432      // [256][72]
#define PO_XV1 36864
#define SMM_PV (55296 * 2)   // 110,592 B

// =====================================================================
// Kernel 1: fused  g_xqh = fp16((x@Q)/32)  AND  g_xTh = fp16(x)^T
// =====================================================================
__global__ void __launch_bounds__(256) k_proj(const float *__restrict__ x,
                                              const float *__restrict__ Q) {
    extern __shared__ float sm[];
    float *Xs = sm;              // [128][68]
    float *Qs = sm + 128 * 68;   // [64][68]
    const int t = threadIdx.x;
    const int row0 = blockIdx.x * 128;
    const int b = row0 >> 12;        // batch
    const int srow = row0 & (S_ - 1);
    const int ty = t >> 3, tx = t & 7;

    float2 acc[4][4];
#pragma unroll
    for (int i = 0; i < 4; i++)
#pragma unroll
        for (int p = 0; p < 4; p++) acc[i][p] = make_float2(0.f, 0.f);

    for (int dc = 0; dc < 16; dc++) {
        const int d0 = dc * 64;
#pragma unroll
        for (int i = 0; i < 8; i++) {
            int f = t + i * 256;
            int r = f >> 4, c4 = f & 15;
            float4 v = *reinterpret_cast<const float4 *>(x + (size_t)(row0 + r) * D_ + d0 + c4 * 4);
            *reinterpret_cast<float4 *>(Xs + r * 68 + c4 * 4) = v;
        }
#pragma unroll
        for (int i = 0; i < 4; i++) {
            int f = t + i * 256;
            int r = f >> 4, c4 = f & 15;
            float4 v = *reinterpret_cast<const float4 *>(Q + (size_t)(d0 + r) * R_ + c4 * 4);
            *reinterpret_cast<float4 *>(Qs + r * 68 + c4 * 4) = v;
        }
        __syncthreads();
        // transposed fp16 write of this X tile: g_xTh[b][d0+dl][srow+r]
#pragma unroll
        for (int i = 0; i < 32; i++) {
            int idx = t + i * 256;           // 0..8191
            int dl = idx >> 7, r = idx & 127;
            g_xTh[((size_t)b * D_ + d0 + dl) * S_ + srow + r] =
                __float2half_rn(Xs[r * 68 + dl]);
        }
#pragma unroll 4
        for (int dd = 0; dd < 64; dd++) {
            float2 aa[4];
#pragma unroll
            for (int i = 0; i < 4; i++) {
                float a = Xs[(ty * 4 + i) * 68 + dd];
                aa[i] = make_float2(a, a);
            }
            float4 q0 = *reinterpret_cast<const float4 *>(Qs + dd * 68 + tx * 8);
            float4 q1 = *reinterpret_cast<const float4 *>(Qs + dd * 68 + tx * 8 + 4);
            float2 bb[4] = {make_float2(q0.x, q0.y), make_float2(q0.z, q0.w),
                            make_float2(q1.x, q1.y), make_float2(q1.z, q1.w)};
#pragma unroll
            for (int i = 0; i < 4; i++)
#pragma unroll
                for (int p = 0; p < 4; p++) ffma2(acc[i][p], aa[i], bb[p]);
        }
        __syncthreads();
    }
    const float scale = 0.03125f;
#pragma unroll
    for (int i = 0; i < 4; i++) {
        __half *dst = g_xqh + (size_t)(row0 + ty * 4 + i) * R_ + tx * 8;
        __half2 h0 = __floats2half2_rn(acc[i][0].x * scale, acc[i][0].y * scale);
        __half2 h1 = __floats2half2_rn(acc[i][1].x * scale, acc[i][1].y * scale);
        __half2 h2 = __floats2half2_rn(acc[i][2].x * scale, acc[i][2].y * scale);
        __half2 h3 = __floats2half2_rn(acc[i][3].x * scale, acc[i][3].y * scale);
        uint4 pk;
        pk.x = *reinterpret_cast<uint32_t *>(&h0);
        pk.y = *reinterpret_cast<uint32_t *>(&h1);
        pk.z = *reinterpret_cast<uint32_t *>(&h2);
        pk.w = *reinterpret_cast<uint32_t *>(&h3);
        *reinterpret_cast<uint4 *>(dst) = pk;
    }
}

// =====================================================================
// Kernel 2: k_qkexp — per (128q x 128n) tile: S = XQq@XQn^T (fp16 mma),
// P~ = fp16(exp(S)) -> g_ph, partial row sums -> g_part[b][nt][q].
// warp grid 2m x 4n, warp tile 64m x 32n (mi=4, nj=4).
// =====================================================================
__global__ void __launch_bounds__(256) k_qkexp() {
    extern __shared__ char smc[];
    __half *smh = reinterpret_cast<__half *>(smc);
    const uint32_t sb = smem_u32(smc);
    const int tid = threadIdx.x, w = tid >> 5, lane = tid & 31;
    const int g = lane >> 2, tg = lane & 3;
    const int wm = w >> 2, wn = w & 3;
    const int m0 = wm * 64, n0 = wn * 32;
    const int b = blockIdx.z, q0 = blockIdx.y * 128, ng = blockIdx.x * 128;

    ld_tileh(sb, QO_A, g_xqh + ((size_t)b * S_ + q0) * R_, R_, 128, tid, 256);
    ld_tileh(sb, QO_B, g_xqh + ((size_t)b * S_ + ng) * R_, R_, 128, tid, 256);
    CP_COMMIT();
    CP_WAIT0();
    __syncthreads();

    float sacc[4][4][4];
#pragma unroll
    for (int mi = 0; mi < 4; mi++)
#pragma unroll
        for (int nj = 0; nj < 4; nj++)
#pragma unroll
            for (int c = 0; c < 4; c++) sacc[mi][nj][c] = 0.f;

    const __half *A = smh + QO_A;
    const __half *Bm = smh + QO_B;
#pragma unroll
    for (int kk = 0; kk < 4; kk++) {
        uint32_t a[4][4], bf[4][2];
        const int c = kk * 16 + 2 * tg;
#pragma unroll
        for (int mi = 0; mi < 4; mi++) {
            int r = m0 + mi * 16 + g;
            a[mi][0] = *reinterpret_cast<const uint32_t *>(A + r * 72 + c);
            a[mi][1] = *reinterpret_cast<const uint32_t *>(A + (r + 8) * 72 + c);
            a[mi][2] = *reinterpret_cast<const uint32_t *>(A + r * 72 + c + 8);
            a[mi][3] = *reinterpret_cast<const uint32_t *>(A + (r + 8) * 72 + c + 8);
        }
#pragma unroll
        for (int nj = 0; nj < 4; nj++) {
            int n = n0 + nj * 8 + g;
            bf[nj][0] = *reinterpret_cast<const uint32_t *>(Bm + n * 72 + c);
            bf[nj][1] = *reinterpret_cast<const uint32_t *>(Bm + n * 72 + c + 8);
        }
#pragma unroll
        for (int mi = 0; mi < 4; mi++)
#pragma unroll
            for (int nj = 0; nj < 4; nj++) mma_f16(sacc[mi][nj], a[mi], bf[nj]);
    }

    // exp, store P~, accumulate row partial sums
    float s0[4], s1[4];
#pragma unroll
    for (int mi = 0; mi < 4; mi++) { s0[mi] = 0.f; s1[mi] = 0.f; }
#pragma unroll
    for (int mi = 0; mi < 4; mi++) {
        size_t r0 = (size_t)b * S_ + q0 + m0 + mi * 16 + g;
#pragma unroll
        for (int nj = 0; nj < 4; nj++) {
            float e0 = __expf(sacc[mi][nj][0]);
            float e1 = __expf(sacc[mi][nj][1]);
            float e2 = __expf(sacc[mi][nj][2]);
            float e3 = __expf(sacc[mi][nj][3]);
            s0[mi] += e0 + e1;
            s1[mi] += e2 + e3;
            int col = ng + n0 + nj * 8 + 2 * tg;
            *reinterpret_cast<__half2 *>(g_ph + r0 * S_ + col) = __floats2half2_rn(e0, e1);
            *reinterpret_cast<__half2 *>(g_ph + (r0 + 8) * S_ + col) = __floats2half2_rn(e2, e3);
        }
    }
    // reduce over tg lanes
#pragma unroll
    for (int off = 1; off <= 2; off <<= 1)
#pragma unroll
        for (int mi = 0; mi < 4; mi++) {
            s0[mi] += __shfl_xor_sync(0xffffffffu, s0[mi], off);
            s1[mi] += __shfl_xor_sync(0xffffffffu, s1[mi], off);
        }
    float *red = reinterpret_cast<float *>(smc + QO_REDB);  // [4 wn][128]
    if (tg == 0) {
#pragma unroll
        for (int mi = 0; mi < 4; mi++) {
            red[wn * 128 + m0 + mi * 16 + g] = s0[mi];
            red[wn * 128 + m0 + mi * 16 + 8 + g] = s1[mi];
        }
    }
    __syncthreads();
    if (tid < 128) {
        float s = red[tid] + red[128 + tid] + red[256 + tid] + red[384 + tid];
        g_part[((size_t)b * 32 + blockIdx.x) * S_ + q0 + tid] = s;
    }
}

// =====================================================================
// Kernel 3: k_red — g_inv = 1 / sum over 32 n-tile partials
// =====================================================================
__global__ void __launch_bounds__(256) k_red() {
    int idx = blockIdx.x * 256 + threadIdx.x;   // 0 .. B*S-1
    int b = idx >> 12, row = idx & (S_ - 1);
    float s = 0.f;
#pragma unroll 8
    for (int nt = 0; nt < 32; nt++) s += g_part[((size_t)b * 32 + nt) * S_ + row];
    g_inv[idx] = 1.0f / s;
}

// =====================================================================
// Kernel 4: k_pv — pure GEMM  Y[q][d] = (P~ @ X) * inv.
// CTA = (q-block 128, d-chunk 256, batch); 256 thr; warp tile 64m x 64n;
// both operand tiles double-buffered; ONE barrier per kb.
// =====================================================================
__global__ void __launch_bounds__(256, 1) k_pv(float *__restrict__ out) {
    extern __shared__ char smc[];
    __half *smh = reinterpret_cast<__half *>(smc);
    const uint32_t sb = smem_u32(smc);
    const int tid = threadIdx.x, w = tid >> 5, lane = tid & 31;
    const int g = lane >> 2, tg = lane & 3;
    const int wm = w >> 2, wn = w & 3;
    const int m0 = wm * 64, n0 = wn * 64;
    const int b = blockIdx.z, q0 = blockIdx.x * 128, d0 = blockIdx.y * 256;

    const __half *ph = g_ph + ((size_t)b * S_ + q0) * S_;       // rows q, cols s
    const __half *xvt = g_xTh + ((size_t)b * D_ + d0) * S_;      // rows d, cols s

    ld_tileh(sb, PO_P0, ph, S_, 128, tid, 256);
    ld_tileh(sb, PO_XV0, xvt, S_, 256, tid, 256);
    CP_COMMIT();
    CP_WAIT0();
    __syncthreads();

    float ri[4][2];
#pragma unroll
    for (int mi = 0; mi < 4; mi++) {
        ri[mi][0] = g_inv[(size_t)b * S_ + q0 + m0 + mi * 16 + g];
        ri[mi][1] = g_inv[(size_t)b * S_ + q0 + m0 + mi * 16 + 8 + g];
    }

    float yacc[4][8][4];
#pragma unroll
    for (int mi = 0; mi < 4; mi++)
#pragma unroll
        for (int nj = 0; nj < 8; nj++)
#pragma unroll
            for (int c = 0; c < 4; c++) yacc[mi][nj][c] = 0.f;

    for (int kb = 0; kb < 64; kb++) {
        if (kb + 1 < 64) {
            int nb = (kb + 1) & 1;
            ld_tileh(sb, nb ? PO_P1 : PO_P0, ph + (size_t)(kb + 1) * 64, S_, 128, tid, 256);
            ld_tileh(sb, nb ? PO_XV1 : PO_XV0, xvt + (size_t)(kb + 1) * 64, S_, 256, tid, 256);
            CP_COMMIT();
        }
        const __half *PS = smh + ((kb & 1) ? PO_P1 : PO_P0);
        const __half *XV = smh + ((kb & 1) ? PO_XV1 : PO_XV0);
#pragma unroll
        for (int kk = 0; kk < 4; kk++) {
            uint32_t a[4][4], bf[8][2];
            const int c = kk * 16 + 2 * tg;
#pragma unroll
            for (int mi = 0; mi < 4; mi++) {
                int r = m0 + mi * 16 + g;
                a[mi][0] = *reinterpret_cast<const uint32_t *>(PS + r * 72 + c);
                a[mi][1] = *reinterpret_cast<const uint32_t *>(PS + (r + 8) * 72 + c);
                a[mi][2] = *reinterpret_cast<const uint32_t *>(PS + r * 72 + c + 8);
                a[mi][3] = *reinterpret_cast<const uint32_t *>(PS + (r + 8) * 72 + c + 8);
            }
#pragma unroll
            for (int nj = 0; nj < 8; nj++) {
                int n = n0 + nj * 8 + g;
                bf[nj][0] = *reinterpret_cast<const uint32_t *>(XV + n * 72 + c);
                bf[nj][1] = *reinterpret_cast<const uint32_t *>(XV + n * 72 + c + 8);
            }
#pragma unroll
            for (int mi = 0; mi < 4; mi++)
#pragma unroll
                for (int nj = 0; nj < 8; nj++) mma_f16(yacc[mi][nj], a[mi], bf[nj]);
        }
        if (kb + 1 < 64) {
            CP_WAIT0();
            __syncthreads();
        }
    }

    // ---- epilogue: normalize + store ----
#pragma unroll
    for (int mi = 0; mi < 4; mi++) {
        size_t rbase = ((size_t)b * S_ + q0 + m0 + mi * 16 + g) * D_ + d0 + n0 + 2 * tg;
#pragma unroll
        for (int nj = 0; nj < 8; nj++) {
            *reinterpret_cast<float2 *>(out + rbase + nj * 8) =
                make_float2(yacc[mi][nj][0] * ri[mi][0], yacc[mi][nj][1] * ri[mi][0]);
            *reinterpret_cast<float2 *>(out + rbase + nj * 8 + (size_t)8 * D_) =
                make_float2(yacc[mi][nj][2] * ri[mi][1], yacc[mi][nj][3] * ri[mi][1]);
        }
    }
}

// =====================================================================
extern "C" void kernel_launch(void *const *d_in, const int *in_sizes, int n_in,
                              void *d_out, int out_size) {
    const float *x = (const float *)d_in[0];
    const float *Q = (const float *)d_in[1];
    float *out = (float *)d_out;

    const int SM1 = (128 * 68 + 64 * 68) * 4;
    cudaFuncSetAttribute(k_proj, cudaFuncAttributeMaxDynamicSharedMemorySize, SM1);
    cudaFuncSetAttribute(k_qkexp, cudaFuncAttributeMaxDynamicSharedMemorySize, SMM_QK);
    cudaFuncSetAttribute(k_pv, cudaFuncAttributeMaxDynamicSharedMemorySize, SMM_PV);

    k_proj<<<(B_ * S_) / 128, 256, SM1>>>(x, Q);
    k_qkexp<<<dim3(S_ / 128, S_ / 128, B_), 256, SMM_QK>>>();
    k_red<<<(B_ * S_) / 256, 256>>>();
    k_pv<<<dim3(S_ / 128, D_ / 256, B_), 256, SMM_PV>>>(out);
}

// round 9
// speedup vs baseline: 1.3238x; 1.0501x over previous
#include <cuda_runtime.h>
#include <cuda_fp16.h>
#include <stdint.h>
#include <math.h>

#define B_ 8
#define S_ 4096
#define D_ 1024
#define R_ 64

// ---------------- scratch (no allocations allowed) ----------------
__device__ __align__(16) __half g_xqh[B_ * S_ * R_];    // 4 MB fp16(x@Q/32)
__device__ __align__(16) __half g_xTh[B_ * D_ * S_];    // 64 MB fp16(x)^T [B][D][S]
__device__ __align__(16) __half g_ph[(size_t)B_ * S_ * S_];  // 268 MB P~ = fp16(exp(S))
__device__ float g_part[B_ * 32 * S_];                   // per-n-tile row sums
__device__ float g_inv[B_ * S_];                         // 1 / sum

// ---------------- helpers ----------------
__device__ __forceinline__ uint32_t smem_u32(const void *p) {
    uint32_t a;
    asm("{ .reg .u64 t; cvta.to.shared.u64 t, %1; cvt.u32.u64 %0, t; }" : "=r"(a) : "l"(p));
    return a;
}
__device__ __forceinline__ void ffma2(float2 &c, const float2 a, const float2 b) {
    asm("fma.rn.f32x2 %0, %1, %2, %0;"
        : "+l"(*reinterpret_cast<unsigned long long *>(&c))
        : "l"(*reinterpret_cast<const unsigned long long *>(&a)),
          "l"(*reinterpret_cast<const unsigned long long *>(&b)));
}
__device__ __forceinline__ void cpa16(uint32_t dst, const void *src) {
    asm volatile("cp.async.cg.shared.global [%0], [%1], 16;" :: "r"(dst), "l"(src));
}
#define CP_COMMIT() asm volatile("cp.async.commit_group;" ::: "memory")
#define CP_WAIT0()  asm volatile("cp.async.wait_group 0;" ::: "memory")

__device__ __forceinline__ void mma_f16(float *d, const uint32_t *a, const uint32_t *b) {
    asm volatile(
        "mma.sync.aligned.m16n8k16.row.col.f32.f16.f16.f32 "
        "{%0,%1,%2,%3}, {%4,%5,%6,%7}, {%8,%9}, {%0,%1,%2,%3};"
        : "+f"(d[0]), "+f"(d[1]), "+f"(d[2]), "+f"(d[3])
        : "r"(a[0]), "r"(a[1]), "r"(a[2]), "r"(a[3]), "r"(b[0]), "r"(b[1]));
}
__device__ __forceinline__ void ldsm_x4(uint32_t &r0, uint32_t &r1, uint32_t &r2,
                                        uint32_t &r3, uint32_t addr) {
    asm volatile("ldmatrix.sync.aligned.m8n8.x4.shared.b16 {%0,%1,%2,%3}, [%4];"
                 : "=r"(r0), "=r"(r1), "=r"(r2), "=r"(r3) : "r"(addr));
}

// tile loader: rows x 64 halves, row stride stride_h (halves), pad-72 dst
__device__ __forceinline__ void ld_tileh(uint32_t sb, int fo_h, const __half *src,
                                         size_t stride_h, int rows, int tid, int nthr) {
    int total = rows * 8;
    for (int idx = tid; idx < total; idx += nthr) {
        int r = idx >> 3, c8 = idx & 7;
        cpa16(sb + (uint32_t)(fo_h + r * 72 + c8 * 8) * 2u,
              src + (size_t)r * stride_h + c8 * 8);
    }
}

// ---------------- k_qkexp smem (half offsets) ----------------
#define QO_A 0            // [128][72]
#define QO_B 9216         // [128][72]
#define QO_REDB 36864     // byte offset: 4x128 floats
#define SMM_QK (36864 + 2048)

// ---------------- k_pv smem (half offsets) ----------------
#define PO_P0 0           // [128][72]
#define PO_P1 9216
#define PO_XV0 18432      // [256][72]
#define PO_XV1 36864
#define SMM_PV (55296 * 2)   // 110,592 B

// =====================================================================
// Kernel 1: fused  g_xqh = fp16((x@Q)/32)  AND  g_xTh = fp16(x)^T
// =====================================================================
__global__ void __launch_bounds__(256) k_proj(const float *__restrict__ x,
                                              const float *__restrict__ Q) {
    extern __shared__ float sm[];
    float *Xs = sm;              // [128][68]
    float *Qs = sm + 128 * 68;   // [64][68]
    const int t = threadIdx.x;
    const int row0 = blockIdx.x * 128;
    const int b = row0 >> 12;
    const int srow = row0 & (S_ - 1);
    const int ty = t >> 3, tx = t & 7;

    float2 acc[4][4];
#pragma unroll
    for (int i = 0; i < 4; i++)
#pragma unroll
        for (int p = 0; p < 4; p++) acc[i][p] = make_float2(0.f, 0.f);

    for (int dc = 0; dc < 16; dc++) {
        const int d0 = dc * 64;
#pragma unroll
        for (int i = 0; i < 8; i++) {
            int f = t + i * 256;
            int r = f >> 4, c4 = f & 15;
            float4 v = *reinterpret_cast<const float4 *>(x + (size_t)(row0 + r) * D_ + d0 + c4 * 4);
            *reinterpret_cast<float4 *>(Xs + r * 68 + c4 * 4) = v;
        }
#pragma unroll
        for (int i = 0; i < 4; i++) {
            int f = t + i * 256;
            int r = f >> 4, c4 = f & 15;
            float4 v = *reinterpret_cast<const float4 *>(Q + (size_t)(d0 + r) * R_ + c4 * 4);
            *reinterpret_cast<float4 *>(Qs + r * 68 + c4 * 4) = v;
        }
        __syncthreads();
#pragma unroll
        for (int i = 0; i < 32; i++) {
            int idx = t + i * 256;
            int dl = idx >> 7, r = idx & 127;
            g_xTh[((size_t)b * D_ + d0 + dl) * S_ + srow + r] =
                __float2half_rn(Xs[r * 68 + dl]);
        }
#pragma unroll 4
        for (int dd = 0; dd < 64; dd++) {
            float2 aa[4];
#pragma unroll
            for (int i = 0; i < 4; i++) {
                float a = Xs[(ty * 4 + i) * 68 + dd];
                aa[i] = make_float2(a, a);
            }
            float4 q0 = *reinterpret_cast<const float4 *>(Qs + dd * 68 + tx * 8);
            float4 q1 = *reinterpret_cast<const float4 *>(Qs + dd * 68 + tx * 8 + 4);
            float2 bb[4] = {make_float2(q0.x, q0.y), make_float2(q0.z, q0.w),
                            make_float2(q1.x, q1.y), make_float2(q1.z, q1.w)};
#pragma unroll
            for (int i = 0; i < 4; i++)
#pragma unroll
                for (int p = 0; p < 4; p++) ffma2(acc[i][p], aa[i], bb[p]);
        }
        __syncthreads();
    }
    const float scale = 0.03125f;
#pragma unroll
    for (int i = 0; i < 4; i++) {
        __half *dst = g_xqh + (size_t)(row0 + ty * 4 + i) * R_ + tx * 8;
        __half2 h0 = __floats2half2_rn(acc[i][0].x * scale, acc[i][0].y * scale);
        __half2 h1 = __floats2half2_rn(acc[i][1].x * scale, acc[i][1].y * scale);
        __half2 h2 = __floats2half2_rn(acc[i][2].x * scale, acc[i][2].y * scale);
        __half2 h3 = __floats2half2_rn(acc[i][3].x * scale, acc[i][3].y * scale);
        uint4 pk;
        pk.x = *reinterpret_cast<uint32_t *>(&h0);
        pk.y = *reinterpret_cast<uint32_t *>(&h1);
        pk.z = *reinterpret_cast<uint32_t *>(&h2);
        pk.w = *reinterpret_cast<uint32_t *>(&h3);
        *reinterpret_cast<uint4 *>(dst) = pk;
    }
}

// =====================================================================
// Kernel 2: k_qkexp — per (128q x 128n): S = XQq@XQn^T, P~=fp16(exp(S)),
// partial row sums. warp grid 2m x 4n, warp tile 64m x 32n. ldmatrix loads.
// =====================================================================
__global__ void __launch_bounds__(256) k_qkexp() {
    extern __shared__ char smc[];
    const uint32_t sb = smem_u32(smc);
    const int tid = threadIdx.x, w = tid >> 5, lane = tid & 31;
    const int g = lane >> 2, tg = lane & 3;
    const int wm = w >> 2, wn = w & 3;
    const int m0 = wm * 64, n0 = wn * 32;
    const int b = blockIdx.z, q0 = blockIdx.y * 128, ng = blockIdx.x * 128;

    // ldmatrix lane offsets
    const int a_row = lane & 15, a_col = (lane >> 4) << 3;
    const int b_row = (lane & 7) + ((lane >> 4) << 3), b_col = lane & 8;

    ld_tileh(sb, QO_A, g_xqh + ((size_t)b * S_ + q0) * R_, R_, 128, tid, 256);
    ld_tileh(sb, QO_B, g_xqh + ((size_t)b * S_ + ng) * R_, R_, 128, tid, 256);
    CP_COMMIT();
    CP_WAIT0();
    __syncthreads();

    float sacc[4][4][4];
#pragma unroll
    for (int mi = 0; mi < 4; mi++)
#pragma unroll
        for (int nj = 0; nj < 4; nj++)
#pragma unroll
            for (int c = 0; c < 4; c++) sacc[mi][nj][c] = 0.f;

#pragma unroll
    for (int kk = 0; kk < 4; kk++) {
        const int c = kk * 16;
        uint32_t a[4][4], bf[4][2];
#pragma unroll
        for (int mi = 0; mi < 4; mi++)
            ldsm_x4(a[mi][0], a[mi][1], a[mi][2], a[mi][3],
                    sb + 2u * (QO_A + (m0 + mi * 16 + a_row) * 72 + c + a_col));
#pragma unroll
        for (int np = 0; np < 2; np++) {
            uint32_t r0, r1, r2, r3;
            ldsm_x4(r0, r1, r2, r3,
                    sb + 2u * (QO_B + (n0 + np * 16 + b_row) * 72 + c + b_col));
            bf[2 * np][0] = r0; bf[2 * np][1] = r1;
            bf[2 * np + 1][0] = r2; bf[2 * np + 1][1] = r3;
        }
#pragma unroll
        for (int mi = 0; mi < 4; mi++)
#pragma unroll
            for (int nj = 0; nj < 4; nj++) mma_f16(sacc[mi][nj], a[mi], bf[nj]);
    }

    float s0[4], s1[4];
#pragma unroll
    for (int mi = 0; mi < 4; mi++) { s0[mi] = 0.f; s1[mi] = 0.f; }
#pragma unroll
    for (int mi = 0; mi < 4; mi++) {
        size_t r0 = (size_t)b * S_ + q0 + m0 + mi * 16 + g;
#pragma unroll
        for (int nj = 0; nj < 4; nj++) {
            float e0 = __expf(sacc[mi][nj][0]);
            float e1 = __expf(sacc[mi][nj][1]);
            float e2 = __expf(sacc[mi][nj][2]);
            float e3 = __expf(sacc[mi][nj][3]);
            s0[mi] += e0 + e1;
            s1[mi] += e2 + e3;
            int col = ng + n0 + nj * 8 + 2 * tg;
            *reinterpret_cast<__half2 *>(g_ph + r0 * S_ + col) = __floats2half2_rn(e0, e1);
            *reinterpret_cast<__half2 *>(g_ph + (r0 + 8) * S_ + col) = __floats2half2_rn(e2, e3);
        }
    }
#pragma unroll
    for (int off = 1; off <= 2; off <<= 1)
#pragma unroll
        for (int mi = 0; mi < 4; mi++) {
            s0[mi] += __shfl_xor_sync(0xffffffffu, s0[mi], off);
            s1[mi] += __shfl_xor_sync(0xffffffffu, s1[mi], off);
        }
    float *red = reinterpret_cast<float *>(smc + QO_REDB);
    if (tg == 0) {
#pragma unroll
        for (int mi = 0; mi < 4; mi++) {
            red[wn * 128 + m0 + mi * 16 + g] = s0[mi];
            red[wn * 128 + m0 + mi * 16 + 8 + g] = s1[mi];
        }
    }
    __syncthreads();
    if (tid < 128) {
        float s = red[tid] + red[128 + tid] + red[256 + tid] + red[384 + tid];
        g_part[((size_t)b * 32 + blockIdx.x) * S_ + q0 + tid] = s;
    }
}

// =====================================================================
// Kernel 3: k_red — g_inv = 1 / sum over 32 n-tile partials
// =====================================================================
__global__ void __launch_bounds__(256) k_red() {
    int idx = blockIdx.x * 256 + threadIdx.x;
    int b = idx >> 12, row = idx & (S_ - 1);
    float s = 0.f;
#pragma unroll 8
    for (int nt = 0; nt < 32; nt++) s += g_part[((size_t)b * 32 + nt) * S_ + row];
    g_inv[idx] = 1.0f / s;
}

// =====================================================================
// Kernel 4: k_pv — pure GEMM  Y[q][d] = (P~ @ X) * inv. ldmatrix loads.
// CTA = (q 128, d 256, batch); warp tile 64m x 64n; double-buffered.
// =====================================================================
__global__ void __launch_bounds__(256, 1) k_pv(float *__restrict__ out) {
    extern __shared__ char smc[];
    const uint32_t sb = smem_u32(smc);
    const int tid = threadIdx.x, w = tid >> 5, lane = tid & 31;
    const int g = lane >> 2, tg = lane & 3;
    const int wm = w >> 2, wn = w & 3;
    const int m0 = wm * 64, n0 = wn * 64;
    const int b = blockIdx.z, q0 = blockIdx.x * 128, d0 = blockIdx.y * 256;

    const int a_row = lane & 15, a_col = (lane >> 4) << 3;
    const int b_row = (lane & 7) + ((lane >> 4) << 3), b_col = lane & 8;

    const __half *ph = g_ph + ((size_t)b * S_ + q0) * S_;
    const __half *xvt = g_xTh + ((size_t)b * D_ + d0) * S_;

    ld_tileh(sb, PO_P0, ph, S_, 128, tid, 256);
    ld_tileh(sb, PO_XV0, xvt, S_, 256, tid, 256);
    CP_COMMIT();
    CP_WAIT0();
    __syncthreads();

    float ri[4][2];
#pragma unroll
    for (int mi = 0; mi < 4; mi++) {
        ri[mi][0] = g_inv[(size_t)b * S_ + q0 + m0 + mi * 16 + g];
        ri[mi][1] = g_inv[(size_t)b * S_ + q0 + m0 + mi * 16 + 8 + g];
    }

    float yacc[4][8][4];
#pragma unroll
    for (int mi = 0; mi < 4; mi++)
#pragma unroll
        for (int nj = 0; nj < 8; nj++)
#pragma unroll
            for (int c = 0; c < 4; c++) yacc[mi][nj][c] = 0.f;

    for (int kb = 0; kb < 64; kb++) {
        if (kb + 1 < 64) {
            int nb = (kb + 1) & 1;
            ld_tileh(sb, nb ? PO_P1 : PO_P0, ph + (size_t)(kb + 1) * 64, S_, 128, tid, 256);
            ld_tileh(sb, nb ? PO_XV1 : PO_XV0, xvt + (size_t)(kb + 1) * 64, S_, 256, tid, 256);
            CP_COMMIT();
        }
        const uint32_t psb = sb + 2u * ((kb & 1) ? PO_P1 : PO_P0);
        const uint32_t xvb = sb + 2u * ((kb & 1) ? PO_XV1 : PO_XV0);
#pragma unroll
        for (int kk = 0; kk < 4; kk++) {
            const int c = kk * 16;
            uint32_t a[4][4], bf[8][2];
#pragma unroll
            for (int mi = 0; mi < 4; mi++)
                ldsm_x4(a[mi][0], a[mi][1], a[mi][2], a[mi][3],
                        psb + 2u * ((m0 + mi * 16 + a_row) * 72 + c + a_col));
#pragma unroll
            for (int np = 0; np < 4; np++) {
                uint32_t r0, r1, r2, r3;
                ldsm_x4(r0, r1, r2, r3,
                        xvb + 2u * ((n0 + np * 16 + b_row) * 72 + c + b_col));
                bf[2 * np][0] = r0; bf[2 * np][1] = r1;
                bf[2 * np + 1][0] = r2; bf[2 * np + 1][1] = r3;
            }
#pragma unroll
            for (int mi = 0; mi < 4; mi++)
#pragma unroll
                for (int nj = 0; nj < 8; nj++) mma_f16(yacc[mi][nj], a[mi], bf[nj]);
        }
        if (kb + 1 < 64) {
            CP_WAIT0();
            __syncthreads();
        }
    }

    // ---- epilogue: normalize + store ----
#pragma unroll
    for (int mi = 0; mi < 4; mi++) {
        size_t rbase = ((size_t)b * S_ + q0 + m0 + mi * 16 + g) * D_ + d0 + n0 + 2 * tg;
#pragma unroll
        for (int nj = 0; nj < 8; nj++) {
            *reinterpret_cast<float2 *>(out + rbase + nj * 8) =
                make_float2(yacc[mi][nj][0] * ri[mi][0], yacc[mi][nj][1] * ri[mi][0]);
            *reinterpret_cast<float2 *>(out + rbase + nj * 8 + (size_t)8 * D_) =
                make_float2(yacc[mi][nj][2] * ri[mi][1], yacc[mi][nj][3] * ri[mi][1]);
        }
    }
}

// =====================================================================
extern "C" void kernel_launch(void *const *d_in, const int *in_sizes, int n_in,
                              void *d_out, int out_size) {
    const float *x = (const float *)d_in[0];
    const float *Q = (const float *)d_in[1];
    float *out = (float *)d_out;

    const int SM1 = (128 * 68 + 64 * 68) * 4;
    cudaFuncSetAttribute(k_proj, cudaFuncAttributeMaxDynamicSharedMemorySize, SM1);
    cudaFuncSetAttribute(k_qkexp, cudaFuncAttributeMaxDynamicSharedMemorySize, SMM_QK);
    cudaFuncSetAttribute(k_pv, cudaFuncAttributeMaxDynamicSharedMemorySize, SMM_PV);

    k_proj<<<(B_ * S_) / 128, 256, SM1>>>(x, Q);
    k_qkexp<<<dim3(S_ / 128, S_ / 128, B_), 256, SMM_QK>>>();
    k_red<<<(B_ * S_) / 256, 256>>>();
    k_pv<<<dim3(S_ / 128, D_ / 256, B_), 256, SMM_PV>>>(out);
}